// round 12
// baseline (speedup 1.0000x reference)
#include <cuda_runtime.h>
#include <cuda_bf16.h>
#include <math.h>
#include <stdint.h>

#define Bv 64
#define Tv 512
#define Iv 512
#define Hv 1024
#define Cv 128
#define G3 (3*Hv)
#define G2 (2*Hv)

// ---------------- static device scratch ----------------
__device__ float g_xw_f[(size_t)Tv*Bv*G3];
__device__ float g_xw_b[(size_t)Tv*Bv*G3];
__device__ float g_xzr [(size_t)Tv*Bv*G2];
__device__ float g_xt  [(size_t)Tv*Bv*Hv];
__device__ float g_att [Tv*Bv];

// packed bf16-pair words (word w = elems 2w (lo16), 2w+1 (hi16))
__device__ uint32_t g_xh[(size_t)32768*256], g_xl[(size_t)32768*256];
__device__ uint32_t g_wif_h[(size_t)3072*256],  g_wif_l[(size_t)3072*256];
__device__ uint32_t g_wib_h[(size_t)3072*256],  g_wib_l[(size_t)3072*256];
__device__ uint32_t g_wizr_h[(size_t)2048*256], g_wizr_l[(size_t)2048*256];
__device__ uint32_t g_wit_h[(size_t)1024*256],  g_wit_l[(size_t)1024*256];
// hidden-state histories, split-bf16 words [t][b][512]
__device__ uint32_t g_hf_h[(size_t)Tv*Bv*512], g_hf_l[(size_t)Tv*Bv*512];
__device__ uint32_t g_hb_h[(size_t)Tv*Bv*512], g_hb_l[(size_t)Tv*Bv*512];
__device__ uint32_t g_ht_h[(size_t)Tv*Bv*512], g_ht_l[(size_t)Tv*Bv*512];

__device__ unsigned g_bar_cnt[3*32];
__device__ unsigned g_bar_gen[3*32];

__device__ __forceinline__ float sigmoidf_(float x) { return 1.0f / (1.0f + expf(-x)); }
__device__ __forceinline__ float lo16f(uint32_t w) { return __uint_as_float(w << 16); }
__device__ __forceinline__ float hi16f(uint32_t w) { return __uint_as_float(w & 0xffff0000u); }
__device__ __forceinline__ uint32_t bfbits(float x) {
    __nv_bfloat16 h = __float2bfloat16(x);
    return (uint32_t)*reinterpret_cast<unsigned short*>(&h);
}
__device__ __forceinline__ void split2(float x0, float x1, uint32_t& wh, uint32_t& wl) {
    uint32_t h0 = bfbits(x0), h1 = bfbits(x1);
    float r0 = x0 - __uint_as_float(h0 << 16);
    float r1 = x1 - __uint_as_float(h1 << 16);
    wh = h0 | (h1 << 16);
    wl = bfbits(r0) | (bfbits(r1) << 16);
}

__device__ __forceinline__ void mma16816(float* d,
    uint32_t a0, uint32_t a1, uint32_t a2, uint32_t a3, uint32_t b0, uint32_t b1) {
    asm volatile(
        "mma.sync.aligned.m16n8k16.row.col.f32.bf16.bf16.f32 "
        "{%0,%1,%2,%3},{%4,%5,%6,%7},{%8,%9},{%0,%1,%2,%3};"
        : "+f"(d[0]), "+f"(d[1]), "+f"(d[2]), "+f"(d[3])
        : "r"(a0), "r"(a1), "r"(a2), "r"(a3), "r"(b0), "r"(b1));
}

// lightweight grid barrier (CG-style release/acquire)
__device__ __forceinline__ void grid_bar(int grp, unsigned nb) {
    __syncthreads();
    if (threadIdx.x == 0) {
        unsigned* cnt = &g_bar_cnt[grp*32];
        unsigned* gen = &g_bar_gen[grp*32];
        unsigned g, old;
        asm volatile("ld.relaxed.gpu.u32 %0, [%1];" : "=r"(g) : "l"(gen) : "memory");
        asm volatile("atom.acq_rel.gpu.add.u32 %0, [%1], %2;"
                     : "=r"(old) : "l"(cnt), "r"(1u) : "memory");
        if (old == nb - 1) {
            asm volatile("st.relaxed.gpu.u32 [%0], %1;" :: "l"(cnt), "r"(0u) : "memory");
            asm volatile("st.release.gpu.u32 [%0], %1;" :: "l"(gen), "r"(g + 1u) : "memory");
        } else {
            unsigned cur;
            do {
                asm volatile("ld.acquire.gpu.u32 %0, [%1];" : "=r"(cur) : "l"(gen) : "memory");
            } while (cur == g);
        }
    }
    __syncthreads();
}

// ============================================================================
// fused converter (ONE launch)
// ============================================================================
#define NXW  ((size_t)32768*256)
#define NWF  ((size_t)3072*256)
#define NWZ  ((size_t)2048*256)
#define NWT  ((size_t)1024*256)
#define NTOT (NXW + 2*NWF + NWZ + NWT)
__global__ void conv_all(const float* __restrict__ x,
                         const float* __restrict__ wif, const float* __restrict__ wib,
                         const float* __restrict__ wzr, const float* __restrict__ wt)
{
    size_t stride = (size_t)gridDim.x * blockDim.x;
    for (size_t i = (size_t)blockIdx.x * blockDim.x + threadIdx.x; i < NTOT; i += stride) {
        const float* src; uint32_t *dh, *dl; size_t si, di;
        if (i < NXW) {
            size_t wi = i & 255, r = i >> 8;
            size_t b = r & 63, t = r >> 6;
            si = (b * Tv + t) * 256 + wi; di = i;
            src = x; dh = g_xh; dl = g_xl;
        } else if (i < NXW + NWF) {
            di = i - NXW; si = di; src = wif; dh = g_wif_h; dl = g_wif_l;
        } else if (i < NXW + 2*NWF) {
            di = i - NXW - NWF; si = di; src = wib; dh = g_wib_h; dl = g_wib_l;
        } else if (i < NXW + 2*NWF + NWZ) {
            di = i - NXW - 2*NWF; si = di; src = wzr; dh = g_wizr_h; dl = g_wizr_l;
        } else {
            di = i - NXW - 2*NWF - NWZ; si = di; src = wt; dh = g_wit_h; dl = g_wit_l;
        }
        float2 v = ((const float2*)src)[si];
        uint32_t wh, wl; split2(v.x, v.y, wh, wl);
        dh[di] = wh; dl[di] = wl;
    }
}

// ============================================================================
// proj via bf16-split mma (R10 winner). m128 x n64 block tile, 128 thr.
// ============================================================================
__global__ void __launch_bounds__(128, 3) proj_mma(
    const uint32_t* __restrict__ Ah, const uint32_t* __restrict__ Al,
    const uint32_t* __restrict__ Wh, const uint32_t* __restrict__ Wl,
    const float* __restrict__ bias, float* __restrict__ out, int N)
{
    extern __shared__ uint32_t ps[];
    uint32_t* sA = ps;            // hi at 0, lo at +4608
    uint32_t* sB = ps + 9216;     // hi at 0, lo at +2304

    const int tid = threadIdx.x, w = tid >> 5, lane = tid & 31;
    const int g = lane >> 2, tg = lane & 3;
    const int m0 = blockIdx.y * 128, n0 = blockIdx.x * 64;

    float D[2][8][4] = {};

    #pragma unroll 1
    for (int st = 0; st < 8; st++) {
        const int kw0 = st * 32;
        __syncthreads();
        #pragma unroll
        for (int q = 0; q < 8; q++) {
            int idx = tid + 128 * q;
            int row = idx >> 3, seg = idx & 7;
            *(uint4*)&sA[row*36 + seg*4]        = *(const uint4*)(Ah + (size_t)(m0+row)*256 + kw0 + seg*4);
            *(uint4*)&sA[4608 + row*36 + seg*4] = *(const uint4*)(Al + (size_t)(m0+row)*256 + kw0 + seg*4);
        }
        #pragma unroll
        for (int q = 0; q < 4; q++) {
            int idx = tid + 128 * q;
            int row = idx >> 3, seg = idx & 7;
            *(uint4*)&sB[row*36 + seg*4]        = *(const uint4*)(Wh + (size_t)(n0+row)*256 + kw0 + seg*4);
            *(uint4*)&sB[2304 + row*36 + seg*4] = *(const uint4*)(Wl + (size_t)(n0+row)*256 + kw0 + seg*4);
        }
        __syncthreads();
        #pragma unroll
        for (int ks = 0; ks < 4; ks++) {
            uint32_t Afh[2][4], Afl[2][4];
            #pragma unroll
            for (int mt = 0; mt < 2; mt++) {
                int ra = (32*w + 16*mt + g) * 36 + ks * 8, rb = ra + 8*36;
                Afh[mt][0] = sA[ra+tg];      Afh[mt][2] = sA[ra+4+tg];
                Afh[mt][1] = sA[rb+tg];      Afh[mt][3] = sA[rb+4+tg];
                Afl[mt][0] = sA[4608+ra+tg]; Afl[mt][2] = sA[4608+ra+4+tg];
                Afl[mt][1] = sA[4608+rb+tg]; Afl[mt][3] = sA[4608+rb+4+tg];
            }
            #pragma unroll
            for (int nt = 0; nt < 8; nt++) {
                int rn = (nt*8 + g) * 36 + ks * 8;
                uint32_t b0h = sB[rn+tg],      b1h = sB[rn+4+tg];
                uint32_t b0l = sB[2304+rn+tg], b1l = sB[2304+rn+4+tg];
                #pragma unroll
                for (int mt = 0; mt < 2; mt++) {
                    mma16816(D[mt][nt], Afh[mt][0],Afh[mt][1],Afh[mt][2],Afh[mt][3], b0h,b1h);
                    mma16816(D[mt][nt], Afh[mt][0],Afh[mt][1],Afh[mt][2],Afh[mt][3], b0l,b1l);
                    mma16816(D[mt][nt], Afl[mt][0],Afl[mt][1],Afl[mt][2],Afl[mt][3], b0h,b1h);
                }
            }
        }
    }

    #pragma unroll
    for (int mt = 0; mt < 2; mt++) {
        int r0 = m0 + 32*w + 16*mt + g, r1 = r0 + 8;
        #pragma unroll
        for (int nt = 0; nt < 8; nt++) {
            int c = n0 + nt*8 + tg*2;
            float2 bi = *(const float2*)(bias + c);
            *(float2*)(out + (size_t)r0 * N + c) = make_float2(D[mt][nt][0]+bi.x, D[mt][nt][1]+bi.y);
            *(float2*)(out + (size_t)r1 * N + c) = make_float2(D[mt][nt][2]+bi.x, D[mt][nt][3]+bi.y);
        }
    }
}

// ============================================================================
// Persistent bidirectional GRU, 512 threads (16 warps = 4/SMSP).
//   128 blocks. dir = bid>>6, 16 hidden cols/block.
//   warp: mt = w&3 (16 rows), ch = (w>>2)&1 (8 cols), kh = w>>3 (2 of 4 ks).
//   kh=1 warps publish D to sH (idle after mainloop); kh=0 accumulate + epilogue.
// ============================================================================
__global__ void __launch_bounds__(512) gru_mma(
    const float* __restrict__ wh_f, const float* __restrict__ wh_b,
    const float* __restrict__ bh_f, const float* __restrict__ bh_b)
{
    extern __shared__ uint32_t smem[];
    uint32_t* sWh = smem;            // 24576 words
    uint32_t* sWl = smem + 24576;    // 24576
    uint32_t* sH  = smem + 49152;    // 8192 (stage bufs; red buffer after mainloop)
    float* red = (float*)sH;

    const int tid = threadIdx.x, w = tid >> 5, lane = tid & 31;
    const int g = lane >> 2, tg = lane & 3;
    const int mt = w & 3, ch = (w >> 2) & 1, kh = w >> 3;
    const int dir = blockIdx.x >> 6;
    const int j0 = (blockIdx.x & 63) * 16;

    const float* wh = dir ? wh_b : wh_f;
    const float* bh = dir ? bh_b : bh_f;
    const float* xw = dir ? g_xw_b : g_xw_f;
    uint32_t* Hh = dir ? g_hb_h : g_hf_h;
    uint32_t* Hl = dir ? g_hb_l : g_hf_l;

    for (int i = tid; i < 48 * 512; i += 512) {
        int vr = i >> 9, wd = i & 511;
        int grow = (vr >> 4) * Hv + j0 + (vr & 15);
        float2 v = *(const float2*)(wh + (size_t)grow * Hv + wd * 2);
        uint32_t wh_, wl_; split2(v.x, v.y, wh_, wl_);
        int ad = vr * 512 + (wd ^ ((vr & 7) << 2));
        sWh[ad] = wh_; sWl[ad] = wl_;
    }
    __syncthreads();

    const int j = j0 + ch * 8 + tg * 2;
    const float2 br_ = *(const float2*)(bh + j);
    const float2 bz_ = *(const float2*)(bh + Hv + j);
    const float2 bn_ = *(const float2*)(bh + 2*Hv + j);
    const int r0 = (16*mt + g) * 32, r1 = r0 + 256;
    const int sza = g << 2;
    const int lrow = tid >> 3, lseg = tid & 7;   // 512 thr -> 64 rows x 8 segs
    const int lgo  = lrow * 512 + lseg * 4;
    const int sad0 = lrow * 32 + ((lseg * 4) ^ ((lrow & 7) << 2));

    for (int s = 0; s < Tv; s++) {
        const int t = dir ? (Tv - 1 - s) : s;
        const int tp = dir ? t + 1 : t - 1;
        const float* xwt = xw + (size_t)t * 64 * G3;

        float2 xrv[2], xzv[2], xnv[2];
        if (kh == 0) {
            #pragma unroll
            for (int rw = 0; rw < 2; rw++) {
                int b = 16*mt + g + 8*rw;
                const float* xr = xwt + (size_t)b * G3;
                xrv[rw] = *(const float2*)(xr + j);
                xzv[rw] = *(const float2*)(xr + Hv + j);
                xnv[rw] = *(const float2*)(xr + 2*Hv + j);
            }
        }

        float D[3][4] = {};
        uint32_t hpw[2] = {0,0}, plw[2] = {0,0};

        if (s) {
            grid_bar(dir, 64);
            const uint32_t* ph = Hh + (size_t)tp * (64*512);
            const uint32_t* pl = Hl + (size_t)tp * (64*512);
            if (kh == 0) {
                #pragma unroll
                for (int rw = 0; rw < 2; rw++) {
                    int b = 16*mt + g + 8*rw;
                    hpw[rw] = ph[(size_t)b*512 + (j>>1)];
                    plw[rw] = pl[(size_t)b*512 + (j>>1)];
                }
            }

            uint4 ah0, al0, bh0, bl0;
            #define LDGST(st, H0, L0) do { \
                H0 = *(const uint4*)(ph + (st)*32 + lgo); \
                L0 = *(const uint4*)(pl + (st)*32 + lgo); \
            } while(0)
            #define STSH(BB, H0, L0) do { \
                uint32_t* bp = sH + (BB)*4096; \
                *(uint4*)(bp + sad0) = H0;   *(uint4*)(bp + sad0 + 2048) = L0; \
            } while(0)
            #define COMPUTE(ST, BB) do { \
                const uint32_t* hb_ = sH + (BB)*4096; \
                _Pragma("unroll") \
                for (int ki = 0; ki < 2; ki++) { \
                    int ks = 2*kh + ki; \
                    int w0 = (ks*8+tg)^sza, w1 = (ks*8+4+tg)^sza; \
                    uint32_t a0h=hb_[r0+w0], a1h=hb_[r1+w0], a2h=hb_[r0+w1], a3h=hb_[r1+w1]; \
                    uint32_t a0l=hb_[2048+r0+w0], a1l=hb_[2048+r1+w0]; \
                    uint32_t a2l=hb_[2048+r0+w1], a3l=hb_[2048+r1+w1]; \
                    _Pragma("unroll") \
                    for (int gate = 0; gate < 3; gate++) { \
                        int vr = gate*16 + ch*8 + g; \
                        int wb0 = vr*512 + (((ST)*32+ks*8+tg) ^ ((vr&7)<<2)); \
                        int wb1 = vr*512 + (((ST)*32+ks*8+4+tg) ^ ((vr&7)<<2)); \
                        uint32_t b0h = sWh[wb0], b1h = sWh[wb1]; \
                        uint32_t b0l = sWl[wb0], b1l = sWl[wb1]; \
                        mma16816(D[gate], a0h,a1h,a2h,a3h, b0h,b1h); \
                        mma16816(D[gate], a0h,a1h,a2h,a3h, b0l,b1l); \
                        mma16816(D[gate], a0l,a1l,a2l,a3l, b0h,b1h); \
                    } \
                } \
            } while(0)

            LDGST(0, ah0, al0);
            LDGST(1, bh0, bl0);
            #pragma unroll 1
            for (int st2 = 0; st2 < 16; st2 += 2) {
                STSH(0, ah0, al0);
                if (st2 < 14) LDGST(st2+2, ah0, al0);
                __syncthreads();
                COMPUTE(st2, 0);
                STSH(1, bh0, bl0);
                if (st2 < 14) LDGST(st2+3, bh0, bl0);
                __syncthreads();
                COMPUTE(st2+1, 1);
            }
            #undef LDGST
            #undef STSH
            #undef COMPUTE

            // combine k-halves via sH (now idle): kh=1 publish, kh=0 accumulate
            __syncthreads();
            if (kh == 1) {
                float* rp = red + ((w - 8) * 32 + lane) * 13;
                #pragma unroll
                for (int gate = 0; gate < 3; gate++)
                    #pragma unroll
                    for (int e = 0; e < 4; e++) rp[gate*4 + e] = D[gate][e];
            }
            __syncthreads();
            if (kh == 0) {
                const float* rp = red + (w * 32 + lane) * 13;
                #pragma unroll
                for (int gate = 0; gate < 3; gate++)
                    #pragma unroll
                    for (int e = 0; e < 4; e++) D[gate][e] += rp[gate*4 + e];
            }
        }

        // epilogue: kh==0 warps
        if (kh == 0) {
            uint32_t* oh = Hh + (size_t)t * (64*512);
            uint32_t* ol = Hl + (size_t)t * (64*512);
            #pragma unroll
            for (int rw = 0; rw < 2; rw++) {
                int b = 16*mt + g + 8*rw;
                float hp0 = 0.f, hp1 = 0.f;
                if (s) {
                    hp0 = lo16f(hpw[rw]) + lo16f(plw[rw]);
                    hp1 = hi16f(hpw[rw]) + hi16f(plw[rw]);
                }
                float r0v = sigmoidf_(xrv[rw].x + D[0][rw*2+0] + br_.x);
                float r1v = sigmoidf_(xrv[rw].y + D[0][rw*2+1] + br_.y);
                float z0 = sigmoidf_(xzv[rw].x + D[1][rw*2+0] + bz_.x);
                float z1 = sigmoidf_(xzv[rw].y + D[1][rw*2+1] + bz_.y);
                float n0 = tanhf(xnv[rw].x + r0v * (D[2][rw*2+0] + bn_.x));
                float n1 = tanhf(xnv[rw].y + r1v * (D[2][rw*2+1] + bn_.y));
                float h0 = (1.f - z0) * n0 + z0 * hp0;
                float h1 = (1.f - z1) * n1 + z1 * hp1;
                uint32_t sh_, sl_; split2(h0, h1, sh_, sl_);
                oh[(size_t)b*512 + (j>>1)] = sh_;
                ol[(size_t)b*512 + (j>>1)] = sl_;
            }
        }
    }
}

// ============================================================================
// attention
// ============================================================================
__global__ void att_kernel(const float* __restrict__ fcw, const float* __restrict__ fcb,
                           float* __restrict__ out_att)
{
    const int t = blockIdx.x;
    const int w = threadIdx.x >> 5, lane = threadIdx.x & 31;
    for (int rep = 0; rep < 8; rep++) {
        int b = w + rep * 8;
        size_t o = (size_t)(t * 64 + b) * 512;
        float acc = 0.0f;
        for (int k = lane; k < 512; k += 32) {
            uint32_t hw = g_hf_h[o + k], lw = g_hf_l[o + k];
            float2 wv = *(const float2*)(fcw + 2 * k);
            acc += (lo16f(hw) + lo16f(lw)) * wv.x + (hi16f(hw) + hi16f(lw)) * wv.y;
            hw = g_hb_h[o + k]; lw = g_hb_l[o + k];
            wv = *(const float2*)(fcw + Hv + 2 * k);
            acc += (lo16f(hw) + lo16f(lw)) * wv.x + (hi16f(hw) + hi16f(lw)) * wv.y;
        }
        #pragma unroll
        for (int of = 16; of; of >>= 1) acc += __shfl_xor_sync(0xffffffffu, acc, of);
        if (lane == 0) {
            float a = sigmoidf_(3.0f * (acc + fcb[0]));
            g_att[t * 64 + b] = a;
            out_att[(size_t)b * Tv + t] = a;
        }
    }
}

// ============================================================================
// Persistent TAGM, 512 threads (16 warps). 128 blocks, 8 cols/block.
//   warp: mt = w&3 (16 rows), kh = w>>2 (1 of 4 ks per stage).
//   kh>0 publish D via sH; kh=0 accumulate + epilogue.
// ============================================================================
__global__ void __launch_bounds__(512) tagm_mma(
    const float* __restrict__ wzr, const float* __restrict__ bzr,
    const float* __restrict__ wt,  const float* __restrict__ bt)
{
    extern __shared__ uint32_t smem[];
    uint32_t* sWh = smem;            // 12288 words
    uint32_t* sWl = smem + 12288;    // 12288
    uint32_t* sH  = smem + 24576;    // 8192 (stage bufs; red buffer after)
    float* red = (float*)sH;

    const int tid = threadIdx.x, w = tid >> 5, lane = tid & 31;
    const int g = lane >> 2, tg = lane & 3;
    const int mt = w & 3, kh = w >> 2;     // kh 0..3
    const int j0 = blockIdx.x * 8;

    for (int i = tid; i < 24 * 512; i += 512) {
        int vr = i >> 9, wd = i & 511;
        int gate = vr >> 3, jj = vr & 7;
        const float* src = (gate < 2) ? (wzr + (size_t)(gate * Hv + j0 + jj) * Hv)
                                      : (wt + (size_t)(j0 + jj) * Hv);
        float2 v = *(const float2*)(src + wd * 2);
        uint32_t wh_, wl_; split2(v.x, v.y, wh_, wl_);
        int ad = vr * 512 + (wd ^ ((vr & 7) << 2));
        sWh[ad] = wh_; sWl[ad] = wl_;
    }
    __syncthreads();

    const int j = j0 + tg * 2;
    const float2 br_ = *(const float2*)(bzr + j);
    const float2 bz_ = *(const float2*)(bzr + Hv + j);
    const float2 bt_ = *(const float2*)(bt + j);
    const int r0 = (16*mt + g) * 32, r1 = r0 + 256;
    const int sza = g << 2;
    const int lrow = tid >> 3, lseg = tid & 7;
    const int lgo  = lrow * 512 + lseg * 4;
    const int sad0 = lrow * 32 + ((lseg * 4) ^ ((lrow & 7) << 2));

    for (int s = 0; s < Tv; s++) {
        float av[2] = {0,0};
        float2 exr[2], exz[2], ext[2];
        if (kh == 0) {
            #pragma unroll
            for (int rw = 0; rw < 2; rw++) {
                int b = 16*mt + g + 8*rw;
                av[rw] = g_att[s * 64 + b];
                exr[rw] = *(const float2*)(g_xzr + (size_t)(s*64 + b) * G2 + j);
                exz[rw] = *(const float2*)(g_xzr + (size_t)(s*64 + b) * G2 + Hv + j);
                ext[rw] = *(const float2*)(g_xt  + (size_t)(s*64 + b) * Hv + j);
            }
        }

        float D[3][4] = {};
        uint32_t hpw[2] = {0,0}, plw[2] = {0,0};

        if (s) {
            grid_bar(2, 128);
            const uint32_t* ph = g_ht_h + (size_t)(s - 1) * (64*512);
            const uint32_t* pl = g_ht_l + (size_t)(s - 1) * (64*512);
            if (kh == 0) {
                #pragma unroll
                for (int rw = 0; rw < 2; rw++) {
                    int b = 16*mt + g + 8*rw;
                    hpw[rw] = ph[(size_t)b*512 + (j>>1)];
                    plw[rw] = pl[(size_t)b*512 + (j>>1)];
                }
            }

            uint4 ah0, al0, bh0, bl0;
            #define LDGST(st, H0, L0) do { \
                H0 = *(const uint4*)(ph + (st)*32 + lgo); \
                L0 = *(const uint4*)(pl + (st)*32 + lgo); \
            } while(0)
            #define STSH(BB, H0, L0) do { \
                uint32_t* bp = sH + (BB)*4096; \
                *(uint4*)(bp + sad0) = H0;   *(uint4*)(bp + sad0 + 2048) = L0; \
            } while(0)
            #define COMPUTE(ST, BB) do { \
                const uint32_t* hb_ = sH + (BB)*4096; \
                int ks = kh; \
                int w0 = (ks*8+tg)^sza, w1 = (ks*8+4+tg)^sza; \
                uint32_t a0h=hb_[r0+w0], a1h=hb_[r1+w0], a2h=hb_[r0+w1], a3h=hb_[r1+w1]; \
                uint32_t a0l=hb_[2048+r0+w0], a1l=hb_[2048+r1+w0]; \
                uint32_t a2l=hb_[2048+r0+w1], a3l=hb_[2048+r1+w1]; \
                _Pragma("unroll") \
                for (int gate = 0; gate < 3; gate++) { \
                    int vr = gate*8 + g; \
                    int wb0 = vr*512 + (((ST)*32+ks*8+tg) ^ (g << 2)); \
                    int wb1 = vr*512 + (((ST)*32+ks*8+4+tg) ^ (g << 2)); \
                    uint32_t b0h = sWh[wb0], b1h = sWh[wb1]; \
                    uint32_t b0l = sWl[wb0], b1l = sWl[wb1]; \
                    mma16816(D[gate], a0h,a1h,a2h,a3h, b0h,b1h); \
                    mma16816(D[gate], a0h,a1h,a2h,a3h, b0l,b1l); \
                    mma16816(D[gate], a0l,a1l,a2l,a3l, b0h,b1h); \
                } \
            } while(0)

            LDGST(0, ah0, al0);
            LDGST(1, bh0, bl0);
            #pragma unroll 1
            for (int st2 = 0; st2 < 16; st2 += 2) {
                STSH(0, ah0, al0);
                if (st2 < 14) LDGST(st2+2, ah0, al0);
                __syncthreads();
                COMPUTE(st2, 0);
                STSH(1, bh0, bl0);
                if (st2 < 14) LDGST(st2+3, bh0, bl0);
                __syncthreads();
                COMPUTE(st2+1, 1);
            }
            #undef LDGST
            #undef STSH
            #undef COMPUTE

            // combine 4 k-quarters: kh>0 publish, kh=0 accumulate
            __syncthreads();
            if (kh) {
                float* rp = red + (((kh-1)*4 + mt) * 32 + lane) * 13;
                #pragma unroll
                for (int gate = 0; gate < 3; gate++)
                    #pragma unroll
                    for (int e = 0; e < 4; e++) rp[gate*4 + e] = D[gate][e];
            }
            __syncthreads();
            if (kh == 0) {
                #pragma unroll
                for (int p = 0; p < 3; p++) {
                    const float* rp = red + ((p*4 + mt) * 32 + lane) * 13;
                    #pragma unroll
                    for (int gate = 0; gate < 3; gate++)
                        #pragma unroll
                        for (int e = 0; e < 4; e++) D[gate][e] += rp[gate*4 + e];
                }
            }
        }

        if (kh == 0) {
            uint32_t* oh = g_ht_h + (size_t)s * (64*512);
            uint32_t* ol = g_ht_l + (size_t)s * (64*512);
            #pragma unroll
            for (int rw = 0; rw < 2; rw++) {
                int b = 16*mt + g + 8*rw;
                float hp0 = 0.f, hp1 = 0.f;
                if (s) {
                    hp0 = lo16f(hpw[rw]) + lo16f(plw[rw]);
                    hp1 = hi16f(hpw[rw]) + hi16f(plw[rw]);
                }
                float r0v = sigmoidf_(exr[rw].x + D[0][rw*2+0] + br_.x);
                float r1v = sigmoidf_(exr[rw].y + D[0][rw*2+1] + br_.y);
                float z0 = sigmoidf_(exz[rw].x + D[1][rw*2+0] + bz_.x);
                float z1 = sigmoidf_(exz[rw].y + D[1][rw*2+1] + bz_.y);
                float t0 = tanhf(ext[rw].x + r0v * (D[2][rw*2+0] + bt_.x));
                float t1 = tanhf(ext[rw].y + r1v * (D[2][rw*2+1] + bt_.y));
                float h0 = av[rw] * (z0 * t0 + (1.f - z0) * hp0);
                float h1 = av[rw] * (z1 * t1 + (1.f - z1) * hp1);
                uint32_t sh_, sl_; split2(h0, h1, sh_, sl_);
                oh[(size_t)b*512 + (j>>1)] = sh_;
                ol[(size_t)b*512 + (j>>1)] = sl_;
            }
        }
    }
}

// ============================================================================
// fc0
// ============================================================================
__global__ void fc0_kernel(const float* __restrict__ w, const float* __restrict__ bias,
                           float* __restrict__ out)
{
    const int b = blockIdx.x;
    const int wp = threadIdx.x >> 5, lane = threadIdx.x & 31;
    size_t o = (size_t)((Tv - 1) * 64 + b) * 512;
    for (int c = wp; c < Cv; c += 8) {
        float acc = 0.0f;
        for (int k = lane; k < 512; k += 32) {
            uint32_t hw = g_ht_h[o + k], lw = g_ht_l[o + k];
            float2 wv = *(const float2*)(w + (size_t)c * Hv + 2 * k);
            acc += (lo16f(hw) + lo16f(lw)) * wv.x + (hi16f(hw) + hi16f(lw)) * wv.y;
        }
        #pragma unroll
        for (int of = 16; of; of >>= 1) acc += __shfl_xor_sync(0xffffffffu, acc, of);
        if (lane == 0) out[(size_t)b * Cv + c] = acc + bias[c];
    }
}

// ============================================================================
extern "C" void kernel_launch(void* const* d_in, const int* in_sizes, int n_in,
                              void* d_out, int out_size)
{
    const float* x        = (const float*)d_in[0];
    const float* att_wi_f = (const float*)d_in[1];
    const float* att_wh_f = (const float*)d_in[2];
    const float* att_bi_f = (const float*)d_in[3];
    const float* att_bh_f = (const float*)d_in[4];
    const float* att_wi_b = (const float*)d_in[5];
    const float* att_wh_b = (const float*)d_in[6];
    const float* att_bi_b = (const float*)d_in[7];
    const float* att_bh_b = (const float*)d_in[8];
    const float* att_fc_w = (const float*)d_in[9];
    const float* att_fc_b = (const float*)d_in[10];
    const float* w_i2h_zr = (const float*)d_in[11];
    const float* b_i2h_zr = (const float*)d_in[12];
    const float* w_h2h_zr = (const float*)d_in[13];
    const float* b_h2h_zr = (const float*)d_in[14];
    const float* w_i2h_t  = (const float*)d_in[15];
    const float* b_i2h_t  = (const float*)d_in[16];
    const float* w_h2h_t  = (const float*)d_in[17];
    const float* b_h2h_t  = (const float*)d_in[18];
    const float* fc0_w    = (const float*)d_in[19];
    const float* fc0_b    = (const float*)d_in[20];

    float* out     = (float*)d_out;
    float* out_att = out + Bv * Cv;

    cudaFuncSetAttribute(proj_mma, cudaFuncAttributeMaxDynamicSharedMemorySize, 55296);
    cudaFuncSetAttribute(gru_mma,  cudaFuncAttributeMaxDynamicSharedMemorySize, 229376);
    cudaFuncSetAttribute(tagm_mma, cudaFuncAttributeMaxDynamicSharedMemorySize, 131072);

    float *p_xwf, *p_xwb, *p_xzr, *p_xt;
    cudaGetSymbolAddress((void**)&p_xwf, g_xw_f);
    cudaGetSymbolAddress((void**)&p_xwb, g_xw_b);
    cudaGetSymbolAddress((void**)&p_xzr, g_xzr);
    cudaGetSymbolAddress((void**)&p_xt,  g_xt);
    uint32_t *p_xh, *p_xl, *p_fh, *p_fl, *p_bh, *p_bl, *p_zh, *p_zl, *p_th, *p_tl;
    cudaGetSymbolAddress((void**)&p_xh, g_xh);     cudaGetSymbolAddress((void**)&p_xl, g_xl);
    cudaGetSymbolAddress((void**)&p_fh, g_wif_h);  cudaGetSymbolAddress((void**)&p_fl, g_wif_l);
    cudaGetSymbolAddress((void**)&p_bh, g_wib_h);  cudaGetSymbolAddress((void**)&p_bl, g_wib_l);
    cudaGetSymbolAddress((void**)&p_zh, g_wizr_h); cudaGetSymbolAddress((void**)&p_zl, g_wizr_l);
    cudaGetSymbolAddress((void**)&p_th, g_wit_h);  cudaGetSymbolAddress((void**)&p_tl, g_wit_l);

    // launch 1: fused conversion
    conv_all<<<2048, 256>>>(x, att_wi_f, att_wi_b, w_i2h_zr, w_i2h_t);

    // launches 2-3: GRU input projections
    proj_mma<<<dim3(48, 256), 128, 55296>>>(p_xh, p_xl, p_fh, p_fl, att_bi_f, p_xwf, G3);
    proj_mma<<<dim3(48, 256), 128, 55296>>>(p_xh, p_xl, p_bh, p_bl, att_bi_b, p_xwb, G3);

    // launch 4: bidirectional GRU (ncu-sampled slot), 512 threads
    gru_mma<<<128, 512, 229376>>>(att_wh_f, att_wh_b, att_bh_f, att_bh_b);

    // launches 5-6: TAGM input projections
    proj_mma<<<dim3(32, 256), 128, 55296>>>(p_xh, p_xl, p_zh, p_zl, b_i2h_zr, p_xzr, G2);
    proj_mma<<<dim3(16, 256), 128, 55296>>>(p_xh, p_xl, p_th, p_tl, b_i2h_t,  p_xt,  Hv);

    // launch 7: attention gate
    att_kernel<<<Tv, 256>>>(att_fc_w, att_fc_b, out_att);

    // launch 8: TAGM recurrence, 512 threads
    tagm_mma<<<128, 512, 131072>>>(w_h2h_zr, b_h2h_zr, w_h2h_t, b_h2h_t);

    // launch 9: final projection
    fc0_kernel<<<Bv, 256>>>(fc0_w, fc0_b, out);
}

// round 13
// speedup vs baseline: 1.1455x; 1.1455x over previous
#include <cuda_runtime.h>
#include <cuda_bf16.h>
#include <math.h>
#include <stdint.h>

#define Bv 64
#define Tv 512
#define Iv 512
#define Hv 1024
#define Cv 128
#define G3 (3*Hv)
#define G2 (2*Hv)

// ---------------- static device scratch ----------------
__device__ float g_xw_f[(size_t)Tv*Bv*G3];
__device__ float g_xw_b[(size_t)Tv*Bv*G3];
__device__ float g_xzr [(size_t)Tv*Bv*G2];
__device__ float g_xt  [(size_t)Tv*Bv*Hv];
__device__ float g_att [Tv*Bv];

// packed bf16-pair words (word w = elems 2w (lo16), 2w+1 (hi16))
__device__ uint32_t g_xh[(size_t)32768*256], g_xl[(size_t)32768*256];
__device__ uint32_t g_wif_h[(size_t)3072*256],  g_wif_l[(size_t)3072*256];
__device__ uint32_t g_wib_h[(size_t)3072*256],  g_wib_l[(size_t)3072*256];
__device__ uint32_t g_wizr_h[(size_t)2048*256], g_wizr_l[(size_t)2048*256];
__device__ uint32_t g_wit_h[(size_t)1024*256],  g_wit_l[(size_t)1024*256];
// hidden-state histories, split-bf16 words [t][b][512]
__device__ uint32_t g_hf_h[(size_t)Tv*Bv*512], g_hf_l[(size_t)Tv*Bv*512];
__device__ uint32_t g_hb_h[(size_t)Tv*Bv*512], g_hb_l[(size_t)Tv*Bv*512];
__device__ uint32_t g_ht_h[(size_t)Tv*Bv*512], g_ht_l[(size_t)Tv*Bv*512];

__device__ unsigned g_bar_cnt[3*32];
__device__ unsigned g_bar_gen[3*32];

__device__ __forceinline__ float sigmoidf_(float x) { return 1.0f / (1.0f + expf(-x)); }
__device__ __forceinline__ float lo16f(uint32_t w) { return __uint_as_float(w << 16); }
__device__ __forceinline__ float hi16f(uint32_t w) { return __uint_as_float(w & 0xffff0000u); }
__device__ __forceinline__ uint32_t bfbits(float x) {
    __nv_bfloat16 h = __float2bfloat16(x);
    return (uint32_t)*reinterpret_cast<unsigned short*>(&h);
}
__device__ __forceinline__ void split2(float x0, float x1, uint32_t& wh, uint32_t& wl) {
    uint32_t h0 = bfbits(x0), h1 = bfbits(x1);
    float r0 = x0 - __uint_as_float(h0 << 16);
    float r1 = x1 - __uint_as_float(h1 << 16);
    wh = h0 | (h1 << 16);
    wl = bfbits(r0) | (bfbits(r1) << 16);
}

__device__ __forceinline__ void mma16816(float* d,
    uint32_t a0, uint32_t a1, uint32_t a2, uint32_t a3, uint32_t b0, uint32_t b1) {
    asm volatile(
        "mma.sync.aligned.m16n8k16.row.col.f32.bf16.bf16.f32 "
        "{%0,%1,%2,%3},{%4,%5,%6,%7},{%8,%9},{%0,%1,%2,%3};"
        : "+f"(d[0]), "+f"(d[1]), "+f"(d[2]), "+f"(d[3])
        : "r"(a0), "r"(a1), "r"(a2), "r"(a3), "r"(b0), "r"(b1));
}

// lightweight grid barrier (CG-style release/acquire)
__device__ __forceinline__ void grid_bar(int grp, unsigned nb) {
    __syncthreads();
    if (threadIdx.x == 0) {
        unsigned* cnt = &g_bar_cnt[grp*32];
        unsigned* gen = &g_bar_gen[grp*32];
        unsigned g, old;
        asm volatile("ld.relaxed.gpu.u32 %0, [%1];" : "=r"(g) : "l"(gen) : "memory");
        asm volatile("atom.acq_rel.gpu.add.u32 %0, [%1], %2;"
                     : "=r"(old) : "l"(cnt), "r"(1u) : "memory");
        if (old == nb - 1) {
            asm volatile("st.relaxed.gpu.u32 [%0], %1;" :: "l"(cnt), "r"(0u) : "memory");
            asm volatile("st.release.gpu.u32 [%0], %1;" :: "l"(gen), "r"(g + 1u) : "memory");
        } else {
            unsigned cur;
            do {
                asm volatile("ld.acquire.gpu.u32 %0, [%1];" : "=r"(cur) : "l"(gen) : "memory");
            } while (cur == g);
        }
    }
    __syncthreads();
}

// ============================================================================
// fused converter (ONE launch)
// ============================================================================
#define NXW  ((size_t)32768*256)
#define NWF  ((size_t)3072*256)
#define NWZ  ((size_t)2048*256)
#define NWT  ((size_t)1024*256)
#define NTOT (NXW + 2*NWF + NWZ + NWT)
__global__ void conv_all(const float* __restrict__ x,
                         const float* __restrict__ wif, const float* __restrict__ wib,
                         const float* __restrict__ wzr, const float* __restrict__ wt)
{
    size_t stride = (size_t)gridDim.x * blockDim.x;
    for (size_t i = (size_t)blockIdx.x * blockDim.x + threadIdx.x; i < NTOT; i += stride) {
        const float* src; uint32_t *dh, *dl; size_t si, di;
        if (i < NXW) {
            size_t wi = i & 255, r = i >> 8;
            size_t b = r & 63, t = r >> 6;
            si = (b * Tv + t) * 256 + wi; di = i;
            src = x; dh = g_xh; dl = g_xl;
        } else if (i < NXW + NWF) {
            di = i - NXW; si = di; src = wif; dh = g_wif_h; dl = g_wif_l;
        } else if (i < NXW + 2*NWF) {
            di = i - NXW - NWF; si = di; src = wib; dh = g_wib_h; dl = g_wib_l;
        } else if (i < NXW + 2*NWF + NWZ) {
            di = i - NXW - 2*NWF; si = di; src = wzr; dh = g_wizr_h; dl = g_wizr_l;
        } else {
            di = i - NXW - 2*NWF - NWZ; si = di; src = wt; dh = g_wit_h; dl = g_wit_l;
        }
        float2 v = ((const float2*)src)[si];
        uint32_t wh, wl; split2(v.x, v.y, wh, wl);
        dh[di] = wh; dl[di] = wl;
    }
}

// ============================================================================
// proj via bf16-split mma (R10 winner, no occupancy clamp).
// ============================================================================
__global__ void __launch_bounds__(128) proj_mma(
    const uint32_t* __restrict__ Ah, const uint32_t* __restrict__ Al,
    const uint32_t* __restrict__ Wh, const uint32_t* __restrict__ Wl,
    const float* __restrict__ bias, float* __restrict__ out, int N)
{
    extern __shared__ uint32_t ps[];
    uint32_t* sA = ps;            // hi at 0, lo at +4608
    uint32_t* sB = ps + 9216;     // hi at 0, lo at +2304

    const int tid = threadIdx.x, w = tid >> 5, lane = tid & 31;
    const int g = lane >> 2, tg = lane & 3;
    const int m0 = blockIdx.y * 128, n0 = blockIdx.x * 64;

    float D[2][8][4] = {};

    #pragma unroll 1
    for (int st = 0; st < 8; st++) {
        const int kw0 = st * 32;
        __syncthreads();
        #pragma unroll
        for (int q = 0; q < 8; q++) {
            int idx = tid + 128 * q;
            int row = idx >> 3, seg = idx & 7;
            *(uint4*)&sA[row*36 + seg*4]        = *(const uint4*)(Ah + (size_t)(m0+row)*256 + kw0 + seg*4);
            *(uint4*)&sA[4608 + row*36 + seg*4] = *(const uint4*)(Al + (size_t)(m0+row)*256 + kw0 + seg*4);
        }
        #pragma unroll
        for (int q = 0; q < 4; q++) {
            int idx = tid + 128 * q;
            int row = idx >> 3, seg = idx & 7;
            *(uint4*)&sB[row*36 + seg*4]        = *(const uint4*)(Wh + (size_t)(n0+row)*256 + kw0 + seg*4);
            *(uint4*)&sB[2304 + row*36 + seg*4] = *(const uint4*)(Wl + (size_t)(n0+row)*256 + kw0 + seg*4);
        }
        __syncthreads();
        #pragma unroll
        for (int ks = 0; ks < 4; ks++) {
            uint32_t Afh[2][4], Afl[2][4];
            #pragma unroll
            for (int mt = 0; mt < 2; mt++) {
                int ra = (32*w + 16*mt + g) * 36 + ks * 8, rb = ra + 8*36;
                Afh[mt][0] = sA[ra+tg];      Afh[mt][2] = sA[ra+4+tg];
                Afh[mt][1] = sA[rb+tg];      Afh[mt][3] = sA[rb+4+tg];
                Afl[mt][0] = sA[4608+ra+tg]; Afl[mt][2] = sA[4608+ra+4+tg];
                Afl[mt][1] = sA[4608+rb+tg]; Afl[mt][3] = sA[4608+rb+4+tg];
            }
            #pragma unroll
            for (int nt = 0; nt < 8; nt++) {
                int rn = (nt*8 + g) * 36 + ks * 8;
                uint32_t b0h = sB[rn+tg],      b1h = sB[rn+4+tg];
                uint32_t b0l = sB[2304+rn+tg], b1l = sB[2304+rn+4+tg];
                #pragma unroll
                for (int mt = 0; mt < 2; mt++) {
                    mma16816(D[mt][nt], Afh[mt][0],Afh[mt][1],Afh[mt][2],Afh[mt][3], b0h,b1h);
                    mma16816(D[mt][nt], Afh[mt][0],Afh[mt][1],Afh[mt][2],Afh[mt][3], b0l,b1l);
                    mma16816(D[mt][nt], Afl[mt][0],Afl[mt][1],Afl[mt][2],Afl[mt][3], b0h,b1h);
                }
            }
        }
    }

    #pragma unroll
    for (int mt = 0; mt < 2; mt++) {
        int r0 = m0 + 32*w + 16*mt + g, r1 = r0 + 8;
        #pragma unroll
        for (int nt = 0; nt < 8; nt++) {
            int c = n0 + nt*8 + tg*2;
            float2 bi = *(const float2*)(bias + c);
            *(float2*)(out + (size_t)r0 * N + c) = make_float2(D[mt][nt][0]+bi.x, D[mt][nt][1]+bi.y);
            *(float2*)(out + (size_t)r1 * N + c) = make_float2(D[mt][nt][2]+bi.x, D[mt][nt][3]+bi.y);
        }
    }
}

// ============================================================================
// Persistent bidirectional GRU, 256 threads (8 warps).
//   warp: mt2 = w&1 (32 rows = two m16 tiles), ch = (w>>1)&1 (8 cols),
//         kh = w>>2 (2 of 4 ks) -> B fragments reused across 2 m-tiles.
//   kh=1 warps publish 24-float D via sH; kh=0 accumulate + epilogue.
// ============================================================================
__global__ void __launch_bounds__(256) gru_mma(
    const float* __restrict__ wh_f, const float* __restrict__ wh_b,
    const float* __restrict__ bh_f, const float* __restrict__ bh_b)
{
    extern __shared__ uint32_t smem[];
    uint32_t* sWh = smem;            // 24576 words
    uint32_t* sWl = smem + 24576;    // 24576
    uint32_t* sH  = smem + 49152;    // 8192 (stage bufs; red buffer after mainloop)
    float* red = (float*)sH;

    const int tid = threadIdx.x, w = tid >> 5, lane = tid & 31;
    const int g = lane >> 2, tg = lane & 3;
    const int mt2 = w & 1, ch = (w >> 1) & 1, kh = w >> 2;
    const int dir = blockIdx.x >> 6;
    const int j0 = (blockIdx.x & 63) * 16;

    const float* wh = dir ? wh_b : wh_f;
    const float* bh = dir ? bh_b : bh_f;
    const float* xw = dir ? g_xw_b : g_xw_f;
    uint32_t* Hh = dir ? g_hb_h : g_hf_h;
    uint32_t* Hl = dir ? g_hb_l : g_hf_l;

    for (int i = tid; i < 48 * 512; i += 256) {
        int vr = i >> 9, wd = i & 511;
        int grow = (vr >> 4) * Hv + j0 + (vr & 15);
        float2 v = *(const float2*)(wh + (size_t)grow * Hv + wd * 2);
        uint32_t wh_, wl_; split2(v.x, v.y, wh_, wl_);
        int ad = vr * 512 + (wd ^ ((vr & 7) << 2));
        sWh[ad] = wh_; sWl[ad] = wl_;
    }
    __syncthreads();

    const int j = j0 + ch * 8 + tg * 2;
    const float2 br_ = *(const float2*)(bh + j);
    const float2 bz_ = *(const float2*)(bh + Hv + j);
    const float2 bn_ = *(const float2*)(bh + 2*Hv + j);
    const int rA0 = (32*mt2 + g) * 32;     // mti tile base: +512*mti, +256 for second m8
    const int sza = g << 2;
    const int lrow = tid >> 3, lseg = tid & 7;
    const int lgo  = lrow * 512 + lseg * 4;
    const int sad0 = lrow * 32 + ((lseg * 4) ^ ((lrow & 7) << 2));
    const int sad1 = sad0 + 1024;

    for (int s = 0; s < Tv; s++) {
        const int t = dir ? (Tv - 1 - s) : s;
        const int tp = dir ? t + 1 : t - 1;
        const float* xwt = xw + (size_t)t * 64 * G3;

        float2 xrv[2][2], xzv[2][2], xnv[2][2];
        if (kh == 0) {
            #pragma unroll
            for (int mti = 0; mti < 2; mti++)
                #pragma unroll
                for (int rw = 0; rw < 2; rw++) {
                    int b = 32*mt2 + 16*mti + g + 8*rw;
                    const float* xr = xwt + (size_t)b * G3;
                    xrv[mti][rw] = *(const float2*)(xr + j);
                    xzv[mti][rw] = *(const float2*)(xr + Hv + j);
                    xnv[mti][rw] = *(const float2*)(xr + 2*Hv + j);
                }
        }

        float D[2][3][4] = {};
        float* Df = &D[0][0][0];
        uint32_t hpw[2][2] = {}, plw[2][2] = {};

        if (s) {
            grid_bar(dir, 64);
            const uint32_t* ph = Hh + (size_t)tp * (64*512);
            const uint32_t* pl = Hl + (size_t)tp * (64*512);
            if (kh == 0) {
                #pragma unroll
                for (int mti = 0; mti < 2; mti++)
                    #pragma unroll
                    for (int rw = 0; rw < 2; rw++) {
                        int b = 32*mt2 + 16*mti + g + 8*rw;
                        hpw[mti][rw] = ph[(size_t)b*512 + (j>>1)];
                        plw[mti][rw] = pl[(size_t)b*512 + (j>>1)];
                    }
            }

            uint4 ah0, al0, ah1, al1, bh0, bl0, bh1, bl1;
            #define LDGST(st, H0, L0, H1, L1) do { \
                const uint32_t* ph_ = ph + (st)*32 + lgo; \
                const uint32_t* pl_ = pl + (st)*32 + lgo; \
                H0 = *(const uint4*)ph_;          L0 = *(const uint4*)pl_; \
                H1 = *(const uint4*)(ph_+16384);  L1 = *(const uint4*)(pl_+16384); \
            } while(0)
            #define STSH(BB, H0, L0, H1, L1) do { \
                uint32_t* bp = sH + (BB)*4096; \
                *(uint4*)(bp + sad0) = H0;        *(uint4*)(bp + sad0 + 2048) = L0; \
                *(uint4*)(bp + sad1) = H1;        *(uint4*)(bp + sad1 + 2048) = L1; \
            } while(0)
            #define COMPUTE(ST, BB) do { \
                const uint32_t* hb_ = sH + (BB)*4096; \
                _Pragma("unroll") \
                for (int ki = 0; ki < 2; ki++) { \
                    int ks = 2*kh + ki; \
                    int w0 = (ks*8+tg)^sza, w1 = (ks*8+4+tg)^sza; \
                    uint32_t aF[2][8]; \
                    _Pragma("unroll") \
                    for (int mti = 0; mti < 2; mti++) { \
                        int rb = rA0 + 512*mti; \
                        aF[mti][0]=hb_[rb+w0];      aF[mti][1]=hb_[rb+256+w0]; \
                        aF[mti][2]=hb_[rb+w1];      aF[mti][3]=hb_[rb+256+w1]; \
                        aF[mti][4]=hb_[2048+rb+w0]; aF[mti][5]=hb_[2048+rb+256+w0]; \
                        aF[mti][6]=hb_[2048+rb+w1]; aF[mti][7]=hb_[2048+rb+256+w1]; \
                    } \
                    _Pragma("unroll") \
                    for (int gate = 0; gate < 3; gate++) { \
                        int vr = gate*16 + ch*8 + g; \
                        int wb0 = vr*512 + (((ST)*32+ks*8+tg) ^ ((vr&7)<<2)); \
                        int wb1 = vr*512 + (((ST)*32+ks*8+4+tg) ^ ((vr&7)<<2)); \
                        uint32_t b0h = sWh[wb0], b1h = sWh[wb1]; \
                        uint32_t b0l = sWl[wb0], b1l = sWl[wb1]; \
                        _Pragma("unroll") \
                        for (int mti = 0; mti < 2; mti++) { \
                            mma16816(D[mti][gate], aF[mti][0],aF[mti][1],aF[mti][2],aF[mti][3], b0h,b1h); \
                            mma16816(D[mti][gate], aF[mti][0],aF[mti][1],aF[mti][2],aF[mti][3], b0l,b1l); \
                            mma16816(D[mti][gate], aF[mti][4],aF[mti][5],aF[mti][6],aF[mti][7], b0h,b1h); \
                        } \
                    } \
                } \
            } while(0)

            LDGST(0, ah0, al0, ah1, al1);
            LDGST(1, bh0, bl0, bh1, bl1);
            #pragma unroll 1
            for (int st2 = 0; st2 < 16; st2 += 2) {
                STSH(0, ah0, al0, ah1, al1);
                if (st2 < 14) LDGST(st2+2, ah0, al0, ah1, al1);
                __syncthreads();
                COMPUTE(st2, 0);
                STSH(1, bh0, bl0, bh1, bl1);
                if (st2 < 14) LDGST(st2+3, bh0, bl0, bh1, bl1);
                __syncthreads();
                COMPUTE(st2+1, 1);
            }
            #undef LDGST
            #undef STSH
            #undef COMPUTE

            // combine k-halves: kh=1 publish 24 floats, kh=0 accumulate
            __syncthreads();
            if (kh == 1) {
                float* rp = red + ((w - 4) * 32 + lane) * 25;
                #pragma unroll
                for (int i = 0; i < 24; i++) rp[i] = Df[i];
            }
            __syncthreads();
            if (kh == 0) {
                const float* rp = red + (w * 32 + lane) * 25;
                #pragma unroll
                for (int i = 0; i < 24; i++) Df[i] += rp[i];
            }
        }

        // epilogue: kh==0 warps (cover 64 rows x 16 cols)
        if (kh == 0) {
            uint32_t* oh = Hh + (size_t)t * (64*512);
            uint32_t* ol = Hl + (size_t)t * (64*512);
            #pragma unroll
            for (int mti = 0; mti < 2; mti++) {
                #pragma unroll
                for (int rw = 0; rw < 2; rw++) {
                    int b = 32*mt2 + 16*mti + g + 8*rw;
                    float hp0 = 0.f, hp1 = 0.f;
                    if (s) {
                        hp0 = lo16f(hpw[mti][rw]) + lo16f(plw[mti][rw]);
                        hp1 = hi16f(hpw[mti][rw]) + hi16f(plw[mti][rw]);
                    }
                    float r0v = sigmoidf_(xrv[mti][rw].x + D[mti][0][rw*2+0] + br_.x);
                    float r1v = sigmoidf_(xrv[mti][rw].y + D[mti][0][rw*2+1] + br_.y);
                    float z0 = sigmoidf_(xzv[mti][rw].x + D[mti][1][rw*2+0] + bz_.x);
                    float z1 = sigmoidf_(xzv[mti][rw].y + D[mti][1][rw*2+1] + bz_.y);
                    float n0 = tanhf(xnv[mti][rw].x + r0v * (D[mti][2][rw*2+0] + bn_.x));
                    float n1 = tanhf(xnv[mti][rw].y + r1v * (D[mti][2][rw*2+1] + bn_.y));
                    float h0 = (1.f - z0) * n0 + z0 * hp0;
                    float h1 = (1.f - z1) * n1 + z1 * hp1;
                    uint32_t sh_, sl_; split2(h0, h1, sh_, sl_);
                    oh[(size_t)b*512 + (j>>1)] = sh_;
                    ol[(size_t)b*512 + (j>>1)] = sl_;
                }
            }
        }
    }
}

// ============================================================================
// attention
// ============================================================================
__global__ void att_kernel(const float* __restrict__ fcw, const float* __restrict__ fcb,
                           float* __restrict__ out_att)
{
    const int t = blockIdx.x;
    const int w = threadIdx.x >> 5, lane = threadIdx.x & 31;
    for (int rep = 0; rep < 8; rep++) {
        int b = w + rep * 8;
        size_t o = (size_t)(t * 64 + b) * 512;
        float acc = 0.0f;
        for (int k = lane; k < 512; k += 32) {
            uint32_t hw = g_hf_h[o + k], lw = g_hf_l[o + k];
            float2 wv = *(const float2*)(fcw + 2 * k);
            acc += (lo16f(hw) + lo16f(lw)) * wv.x + (hi16f(hw) + hi16f(lw)) * wv.y;
            hw = g_hb_h[o + k]; lw = g_hb_l[o + k];
            wv = *(const float2*)(fcw + Hv + 2 * k);
            acc += (lo16f(hw) + lo16f(lw)) * wv.x + (hi16f(hw) + hi16f(lw)) * wv.y;
        }
        #pragma unroll
        for (int of = 16; of; of >>= 1) acc += __shfl_xor_sync(0xffffffffu, acc, of);
        if (lane == 0) {
            float a = sigmoidf_(3.0f * (acc + fcb[0]));
            g_att[t * 64 + b] = a;
            out_att[(size_t)b * Tv + t] = a;
        }
    }
}

// ============================================================================
// Persistent TAGM, 256 threads (8 warps). 128 blocks, 8 cols/block.
//   warp: mt2 = w&1 (32 rows = two m16 tiles), kh = w>>1 (1 of 4 ks).
//   kh>0 publish 24-float D via sH; kh=0 accumulate + epilogue.
// ============================================================================
__global__ void __launch_bounds__(256) tagm_mma(
    const float* __restrict__ wzr, const float* __restrict__ bzr,
    const float* __restrict__ wt,  const float* __restrict__ bt)
{
    extern __shared__ uint32_t smem[];
    uint32_t* sWh = smem;            // 12288 words
    uint32_t* sWl = smem + 12288;    // 12288
    uint32_t* sH  = smem + 24576;    // 8192 (stage bufs; red buffer after)
    float* red = (float*)sH;

    const int tid = threadIdx.x, w = tid >> 5, lane = tid & 31;
    const int g = lane >> 2, tg = lane & 3;
    const int mt2 = w & 1, kh = w >> 1;     // kh 0..3
    const int j0 = blockIdx.x * 8;

    for (int i = tid; i < 24 * 512; i += 256) {
        int vr = i >> 9, wd = i & 511;
        int gate = vr >> 3, jj = vr & 7;
        const float* src = (gate < 2) ? (wzr + (size_t)(gate * Hv + j0 + jj) * Hv)
                                      : (wt + (size_t)(j0 + jj) * Hv);
        float2 v = *(const float2*)(src + wd * 2);
        uint32_t wh_, wl_; split2(v.x, v.y, wh_, wl_);
        int ad = vr * 512 + (wd ^ ((vr & 7) << 2));
        sWh[ad] = wh_; sWl[ad] = wl_;
    }
    __syncthreads();

    const int j = j0 + tg * 2;
    const float2 br_ = *(const float2*)(bzr + j);
    const float2 bz_ = *(const float2*)(bzr + Hv + j);
    const float2 bt_ = *(const float2*)(bt + j);
    const int rA0 = (32*mt2 + g) * 32;
    const int sza = g << 2;
    const int lrow = tid >> 3, lseg = tid & 7;
    const int lgo  = lrow * 512 + lseg * 4;
    const int sad0 = lrow * 32 + ((lseg * 4) ^ ((lrow & 7) << 2));
    const int sad1 = sad0 + 1024;

    for (int s = 0; s < Tv; s++) {
        float av[2][2] = {};
        float2 exr[2][2], exz[2][2], ext[2][2];
        if (kh == 0) {
            #pragma unroll
            for (int mti = 0; mti < 2; mti++)
                #pragma unroll
                for (int rw = 0; rw < 2; rw++) {
                    int b = 32*mt2 + 16*mti + g + 8*rw;
                    av[mti][rw] = g_att[s * 64 + b];
                    exr[mti][rw] = *(const float2*)(g_xzr + (size_t)(s*64 + b) * G2 + j);
                    exz[mti][rw] = *(const float2*)(g_xzr + (size_t)(s*64 + b) * G2 + Hv + j);
                    ext[mti][rw] = *(const float2*)(g_xt  + (size_t)(s*64 + b) * Hv + j);
                }
        }

        float D[2][3][4] = {};
        float* Df = &D[0][0][0];
        uint32_t hpw[2][2] = {}, plw[2][2] = {};

        if (s) {
            grid_bar(2, 128);
            const uint32_t* ph = g_ht_h + (size_t)(s - 1) * (64*512);
            const uint32_t* pl = g_ht_l + (size_t)(s - 1) * (64*512);
            if (kh == 0) {
                #pragma unroll
                for (int mti = 0; mti < 2; mti++)
                    #pragma unroll
                    for (int rw = 0; rw < 2; rw++) {
                        int b = 32*mt2 + 16*mti + g + 8*rw;
                        hpw[mti][rw] = ph[(size_t)b*512 + (j>>1)];
                        plw[mti][rw] = pl[(size_t)b*512 + (j>>1)];
                    }
            }

            uint4 ah0, al0, ah1, al1, bh0, bl0, bh1, bl1;
            #define LDGST(st, H0, L0, H1, L1) do { \
                const uint32_t* ph_ = ph + (st)*32 + lgo; \
                const uint32_t* pl_ = pl + (st)*32 + lgo; \
                H0 = *(const uint4*)ph_;          L0 = *(const uint4*)pl_; \
                H1 = *(const uint4*)(ph_+16384);  L1 = *(const uint4*)(pl_+16384); \
            } while(0)
            #define STSH(BB, H0, L0, H1, L1) do { \
                uint32_t* bp = sH + (BB)*4096; \
                *(uint4*)(bp + sad0) = H0;        *(uint4*)(bp + sad0 + 2048) = L0; \
                *(uint4*)(bp + sad1) = H1;        *(uint4*)(bp + sad1 + 2048) = L1; \
            } while(0)
            #define COMPUTE(ST, BB) do { \
                const uint32_t* hb_ = sH + (BB)*4096; \
                int ks = kh; \
                int w0 = (ks*8+tg)^sza, w1 = (ks*8+4+tg)^sza; \
                uint32_t aF[2][8]; \
                _Pragma("unroll") \
                for (int mti = 0; mti < 2; mti++) { \
                    int rb = rA0 + 512*mti; \
                    aF[mti][0]=hb_[rb+w0];      aF[mti][1]=hb_[rb+256+w0]; \
                    aF[mti][2]=hb_[rb+w1];      aF[mti][3]=hb_[rb+256+w1]; \
                    aF[mti][4]=hb_[2048+rb+w0]; aF[mti][5]=hb_[2048+rb+256+w0]; \
                    aF[mti][6]=hb_[2048+rb+w1]; aF[mti][7]=hb_[2048+rb+256+w1]; \
                } \
                _Pragma("unroll") \
                for (int gate = 0; gate < 3; gate++) { \
                    int vr = gate*8 + g; \
                    int wb0 = vr*512 + (((ST)*32+ks*8+tg) ^ sza); \
                    int wb1 = vr*512 + (((ST)*32+ks*8+4+tg) ^ sza); \
                    uint32_t b0h = sWh[wb0], b1h = sWh[wb1]; \
                    uint32_t b0l = sWl[wb0], b1l = sWl[wb1]; \
                    _Pragma("unroll") \
                    for (int mti = 0; mti < 2; mti++) { \
                        mma16816(D[mti][gate], aF[mti][0],aF[mti][1],aF[mti][2],aF[mti][3], b0h,b1h); \
                        mma16816(D[mti][gate], aF[mti][0],aF[mti][1],aF[mti][2],aF[mti][3], b0l,b1l); \
                        mma16816(D[mti][gate], aF[mti][4],aF[mti][5],aF[mti][6],aF[mti][7], b0h,b1h); \
                    } \
                } \
            } while(0)

            LDGST(0, ah0, al0, ah1, al1);
            LDGST(1, bh0, bl0, bh1, bl1);
            #pragma unroll 1
            for (int st2 = 0; st2 < 16; st2 += 2) {
                STSH(0, ah0, al0, ah1, al1);
                if (st2 < 14) LDGST(st2+2, ah0, al0, ah1, al1);
                __syncthreads();
                COMPUTE(st2, 0);
                STSH(1, bh0, bl0, bh1, bl1);
                if (st2 < 14) LDGST(st2+3, bh0, bl0, bh1, bl1);
                __syncthreads();
                COMPUTE(st2+1, 1);
            }
            #undef LDGST
            #undef STSH
            #undef COMPUTE

            // combine 4 k-quarters: kh>0 publish, kh=0 accumulate
            __syncthreads();
            if (kh) {
                float* rp = red + (((kh-1)*2 + mt2) * 32 + lane) * 25;
                #pragma unroll
                for (int i = 0; i < 24; i++) rp[i] = Df[i];
            }
            __syncthreads();
            if (kh == 0) {
                #pragma unroll
                for (int p = 0; p < 3; p++) {
                    const float* rp = red + ((p*2 + mt2) * 32 + lane) * 25;
                    #pragma unroll
                    for (int i = 0; i < 24; i++) Df[i] += rp[i];
                }
            }
        }

        if (kh == 0) {
            uint32_t* oh = g_ht_h + (size_t)s * (64*512);
            uint32_t* ol = g_ht_l + (size_t)s * (64*512);
            #pragma unroll
            for (int mti = 0; mti < 2; mti++) {
                #pragma unroll
                for (int rw = 0; rw < 2; rw++) {
                    int b = 32*mt2 + 16*mti + g + 8*rw;
                    float hp0 = 0.f, hp1 = 0.f;
                    if (s) {
                        hp0 = lo16f(hpw[mti][rw]) + lo16f(plw[mti][rw]);
                        hp1 = hi16f(hpw[mti][rw]) + hi16f(plw[mti][rw]);
                    }
                    float r0v = sigmoidf_(exr[mti][rw].x + D[mti][0][rw*2+0] + br_.x);
                    float r1v = sigmoidf_(exr[mti][rw].y + D[mti][0][rw*2+1] + br_.y);
                    float z0 = sigmoidf_(exz[mti][rw].x + D[mti][1][rw*2+0] + bz_.x);
                    float z1 = sigmoidf_(exz[mti][rw].y + D[mti][1][rw*2+1] + bz_.y);
                    float t0 = tanhf(ext[mti][rw].x + r0v * (D[mti][2][rw*2+0] + bt_.x));
                    float t1 = tanhf(ext[mti][rw].y + r1v * (D[mti][2][rw*2+1] + bt_.y));
                    float h0 = av[mti][rw] * (z0 * t0 + (1.f - z0) * hp0);
                    float h1 = av[mti][rw] * (z1 * t1 + (1.f - z1) * hp1);
                    uint32_t sh_, sl_; split2(h0, h1, sh_, sl_);
                    oh[(size_t)b*512 + (j>>1)] = sh_;
                    ol[(size_t)b*512 + (j>>1)] = sl_;
                }
            }
        }
    }
}

// ============================================================================
// fc0
// ============================================================================
__global__ void fc0_kernel(const float* __restrict__ w, const float* __restrict__ bias,
                           float* __restrict__ out)
{
    const int b = blockIdx.x;
    const int wp = threadIdx.x >> 5, lane = threadIdx.x & 31;
    size_t o = (size_t)((Tv - 1) * 64 + b) * 512;
    for (int c = wp; c < Cv; c += 8) {
        float acc = 0.0f;
        for (int k = lane; k < 512; k += 32) {
            uint32_t hw = g_ht_h[o + k], lw = g_ht_l[o + k];
            float2 wv = *(const float2*)(w + (size_t)c * Hv + 2 * k);
            acc += (lo16f(hw) + lo16f(lw)) * wv.x + (hi16f(hw) + hi16f(lw)) * wv.y;
        }
        #pragma unroll
        for (int of = 16; of; of >>= 1) acc += __shfl_xor_sync(0xffffffffu, acc, of);
        if (lane == 0) out[(size_t)b * Cv + c] = acc + bias[c];
    }
}

// ============================================================================
extern "C" void kernel_launch(void* const* d_in, const int* in_sizes, int n_in,
                              void* d_out, int out_size)
{
    const float* x        = (const float*)d_in[0];
    const float* att_wi_f = (const float*)d_in[1];
    const float* att_wh_f = (const float*)d_in[2];
    const float* att_bi_f = (const float*)d_in[3];
    const float* att_bh_f = (const float*)d_in[4];
    const float* att_wi_b = (const float*)d_in[5];
    const float* att_wh_b = (const float*)d_in[6];
    const float* att_bi_b = (const float*)d_in[7];
    const float* att_bh_b = (const float*)d_in[8];
    const float* att_fc_w = (const float*)d_in[9];
    const float* att_fc_b = (const float*)d_in[10];
    const float* w_i2h_zr = (const float*)d_in[11];
    const float* b_i2h_zr = (const float*)d_in[12];
    const float* w_h2h_zr = (const float*)d_in[13];
    const float* b_h2h_zr = (const float*)d_in[14];
    const float* w_i2h_t  = (const float*)d_in[15];
    const float* b_i2h_t  = (const float*)d_in[16];
    const float* w_h2h_t  = (const float*)d_in[17];
    const float* b_h2h_t  = (const float*)d_in[18];
    const float* fc0_w    = (const float*)d_in[19];
    const float* fc0_b    = (const float*)d_in[20];

    float* out     = (float*)d_out;
    float* out_att = out + Bv * Cv;

    cudaFuncSetAttribute(proj_mma, cudaFuncAttributeMaxDynamicSharedMemorySize, 55296);
    cudaFuncSetAttribute(gru_mma,  cudaFuncAttributeMaxDynamicSharedMemorySize, 229376);
    cudaFuncSetAttribute(tagm_mma, cudaFuncAttributeMaxDynamicSharedMemorySize, 131072);

    float *p_xwf, *p_xwb, *p_xzr, *p_xt;
    cudaGetSymbolAddress((void**)&p_xwf, g_xw_f);
    cudaGetSymbolAddress((void**)&p_xwb, g_xw_b);
    cudaGetSymbolAddress((void**)&p_xzr, g_xzr);
    cudaGetSymbolAddress((void**)&p_xt,  g_xt);
    uint32_t *p_xh, *p_xl, *p_fh, *p_fl, *p_bh, *p_bl, *p_zh, *p_zl, *p_th, *p_tl;
    cudaGetSymbolAddress((void**)&p_xh, g_xh);     cudaGetSymbolAddress((void**)&p_xl, g_xl);
    cudaGetSymbolAddress((void**)&p_fh, g_wif_h);  cudaGetSymbolAddress((void**)&p_fl, g_wif_l);
    cudaGetSymbolAddress((void**)&p_bh, g_wib_h);  cudaGetSymbolAddress((void**)&p_bl, g_wib_l);
    cudaGetSymbolAddress((void**)&p_zh, g_wizr_h); cudaGetSymbolAddress((void**)&p_zl, g_wizr_l);
    cudaGetSymbolAddress((void**)&p_th, g_wit_h);  cudaGetSymbolAddress((void**)&p_tl, g_wit_l);

    // launch 1: fused conversion
    conv_all<<<2048, 256>>>(x, att_wi_f, att_wi_b, w_i2h_zr, w_i2h_t);

    // launches 2-3: GRU input projections
    proj_mma<<<dim3(48, 256), 128, 55296>>>(p_xh, p_xl, p_fh, p_fl, att_bi_f, p_xwf, G3);
    proj_mma<<<dim3(48, 256), 128, 55296>>>(p_xh, p_xl, p_bh, p_bl, att_bi_b, p_xwb, G3);

    // launch 4: bidirectional GRU (ncu-sampled slot)
    gru_mma<<<128, 256, 229376>>>(att_wh_f, att_wh_b, att_bh_f, att_bh_b);

    // launches 5-6: TAGM input projections
    proj_mma<<<dim3(32, 256), 128, 55296>>>(p_xh, p_xl, p_zh, p_zl, b_i2h_zr, p_xzr, G2);
    proj_mma<<<dim3(16, 256), 128, 55296>>>(p_xh, p_xl, p_th, p_tl, b_i2h_t,  p_xt,  Hv);

    // launch 7: attention gate
    att_kernel<<<Tv, 256>>>(att_fc_w, att_fc_b, out_att);

    // launch 8: TAGM recurrence
    tagm_mma<<<128, 256, 131072>>>(w_h2h_zr, b_h2h_zr, w_h2h_t, b_h2h_t);

    // launch 9: final projection
    fc0_kernel<<<Bv, 256>>>(fc0_w, fc0_b, out);
}